// round 1
// baseline (speedup 1.0000x reference)
#include <cuda_runtime.h>
#include <cuda_bf16.h>
#include <cstdint>

#define NUM_USER 200000
#define NUM_QUESTION 20000
#define NUM_CONCEPT 128
#define DIM_HIDDEN 512
#define H2 256
#define BATCH 16384

// ---------------- scratch (device globals; no allocations allowed) ----------
__device__ float g_AuT[NUM_CONCEPT * BATCH];   // post*q, feature-major
__device__ float g_AiT[NUM_CONCEPT * BATCH];   // sigmoid(diff)*q, feature-major
__device__ float g_disc[BATCH];
__device__ float g_XT[DIM_HIDDEN * BATCH];     // layer-1 output, feature-major
__device__ float g_HT[H2 * BATCH];             // layer-2 output, feature-major

// ---------------- graph structure (replicated numpy RandomState(0)) ---------
struct Graph {
    int E;
    unsigned char lp[NUM_CONCEPT];
    short off[NUM_CONCEPT];
    unsigned char pred[NUM_CONCEPT][3];
};

// Host-side exact replication of numpy legacy MT19937 + bounded-int streams.
struct MT19937 {
    uint32_t mt[624];
    int mti;
    void seed(uint32_t s) {
        mt[0] = s;
        for (int i = 1; i < 624; i++)
            mt[i] = 1812433253u * (mt[i - 1] ^ (mt[i - 1] >> 30)) + (uint32_t)i;
        mti = 624;
    }
    uint32_t next() {
        if (mti >= 624) {
            for (int i = 0; i < 624; i++) {
                uint32_t y = (mt[i] & 0x80000000u) | (mt[(i + 1) % 624] & 0x7fffffffu);
                uint32_t v = mt[(i + 397) % 624] ^ (y >> 1);
                if (y & 1u) v ^= 0x9908b0dfu;
                mt[i] = v;
            }
            mti = 0;
        }
        uint32_t y = mt[mti++];
        y ^= y >> 11;
        y ^= (y << 7) & 0x9d2c5680u;
        y ^= (y << 15) & 0xefc60000u;
        y ^= y >> 18;
        return y;
    }
    // value uniform in [0, mx], masked rejection on 32-bit draws
    // (numpy legacy: randint small-range path AND shuffle's random_interval)
    uint32_t interval(uint32_t mx) {
        if (mx == 0) return 0;
        uint32_t mask = mx;
        mask |= mask >> 1; mask |= mask >> 2; mask |= mask >> 4;
        mask |= mask >> 8; mask |= mask >> 16;
        uint32_t v;
        do { v = next() & mask; } while (v > mx);
        return v;
    }
};

static void build_graph(Graph& g) {
    MT19937 r;
    r.seed(0u);
    int E = 0;
    for (int k = 0; k < NUM_CONCEPT; k++) {
        int l = 0;
        if (k > 0) {
            int hi = (k < 3) ? k : 3;          // randint(0, min(k,3)+1) -> [0, hi]
            l = (int)r.interval((uint32_t)hi);
        }
        g.lp[k] = (unsigned char)l;
        g.off[k] = (short)E;
        g.pred[k][0] = g.pred[k][1] = g.pred[k][2] = 0;
        if (l > 0) {
            // rng.choice(k, size=l, replace=False) == permutation(k)[:l]
            int perm[NUM_CONCEPT];
            for (int i = 0; i < k; i++) perm[i] = i;
            for (int i = k - 1; i >= 1; i--) {
                int j = (int)r.interval((uint32_t)i);
                int t = perm[i]; perm[i] = perm[j]; perm[j] = t;
            }
            int p[3];
            for (int j = 0; j < l; j++) p[j] = perm[j];
            for (int a = 0; a < l; a++)
                for (int b = a + 1; b < l; b++)
                    if (p[b] < p[a]) { int t = p[a]; p[a] = p[b]; p[b] = t; }
            for (int j = 0; j < l; j++) g.pred[k][j] = (unsigned char)p[j];
        }
        E += l;
    }
    g.E = E;
}

// ---------------- device helpers --------------------------------------------
__device__ __forceinline__ float sigmoidf(float x) {
    return 1.0f / (1.0f + expf(-x));
}

// ---------------- kernel 1: posterior DAG + activation build ----------------
__global__ __launch_bounds__(64) void posterior_kernel(
    Graph g,
    const int* __restrict__ user_id, const int* __restrict__ question_id,
    const float* __restrict__ priori, const float* __restrict__ condi_p,
    const float* __restrict__ condi_n, const float* __restrict__ item_diff,
    const float* __restrict__ item_disc, const float* __restrict__ q_table,
    int E)
{
    __shared__ float post[NUM_CONCEPT * 64];   // [k][lane], 32 KB
    const int tid = threadIdx.x;
    const int b = blockIdx.x * 64 + tid;
    const int u = user_id[b];
    const int q = question_id[b];
    const float* __restrict__ prow = priori + (size_t)u * NUM_CONCEPT;
    const float* __restrict__ cpr  = condi_p + (size_t)u * E;
    const float* __restrict__ cnr  = condi_n + (size_t)u * E;

    for (int k = 0; k < NUM_CONCEPT; k++) {
        const int l = g.lp[k];
        float pk;
        if (l == 0) {
            pk = sigmoidf(prow[k]);
        } else {
            const int o = g.off[k];
            float prod = 1.0f;
            #pragma unroll 3
            for (int j = 0; j < 3; j++) {
                if (j >= l) break;
                float pr = post[(int)g.pred[k][j] * 64 + tid];
                float cp = sigmoidf(cpr[o + j]);
                float cn = sigmoidf(cnr[o + j]);
                if (l == 2) { cp = sqrtf(cp); cn = sqrtf(cn); }
                else if (l == 3) {
                    cp = powf(cp, 0.33333334f);
                    cn = powf(cn, 0.33333334f);
                }
                prod *= cp * pr + cn * (1.0f - pr);
            }
            pk = prod;
        }
        post[k * 64 + tid] = pk;
    }

    g_disc[b] = sigmoidf(item_disc[q]);

    const float* __restrict__ drow = item_diff + (size_t)q * NUM_CONCEPT;
    const float* __restrict__ qrow = q_table + (size_t)q * NUM_CONCEPT;
    for (int k = 0; k < NUM_CONCEPT; k++) {
        float qv = qrow[k];
        g_AuT[(size_t)k * BATCH + b] = post[k * 64 + tid] * qv;
        g_AiT[(size_t)k * BATCH + b] = sigmoidf(drow[k]) * qv;
    }
}

// ---------------- kernel 2: dual GEMM (user/item factors) + fused epilogue --
// C_T[n][m] over m-tile 128, n-tile 64; thread = 8(m) x 4(n), 256 threads.
__global__ __launch_bounds__(256) void gemm_layer1(
    const float* __restrict__ Wu, const float* __restrict__ Wi,
    const float* __restrict__ bu, const float* __restrict__ bi)
{
    const int KT = 16;
    __shared__ float sAu[KT][128];
    __shared__ float sAi[KT][128];
    __shared__ float sWu[64][20];
    __shared__ float sWi[64][20];

    const int tid = threadIdx.x;
    const int tx = tid & 15;       // m-group (m = m0 + tx + 16*i)
    const int ty = tid >> 4;       // n-group (n = n0 + ty*4 + j)
    const int m0 = blockIdx.x * 128;
    const int n0 = blockIdx.y * 64;

    float accU[8][4], accI[8][4];
    #pragma unroll
    for (int i = 0; i < 8; i++)
        #pragma unroll
        for (int j = 0; j < 4; j++) { accU[i][j] = 0.f; accI[i][j] = 0.f; }

    for (int k0 = 0; k0 < NUM_CONCEPT; k0 += KT) {
        #pragma unroll
        for (int r = 0; r < 2; r++) {
            int idx = tid + 256 * r;            // 0..511 float4s
            int kk = idx >> 5, mv = idx & 31;
            *(float4*)&sAu[kk][mv * 4] =
                *(const float4*)&g_AuT[(size_t)(k0 + kk) * BATCH + m0 + mv * 4];
            *(float4*)&sAi[kk][mv * 4] =
                *(const float4*)&g_AiT[(size_t)(k0 + kk) * BATCH + m0 + mv * 4];
        }
        {
            int n = tid >> 2, kv = tid & 3;
            *(float4*)&sWu[n][kv * 4] =
                *(const float4*)&Wu[(size_t)(n0 + n) * NUM_CONCEPT + k0 + kv * 4];
            *(float4*)&sWi[n][kv * 4] =
                *(const float4*)&Wi[(size_t)(n0 + n) * NUM_CONCEPT + k0 + kv * 4];
        }
        __syncthreads();
        #pragma unroll
        for (int kk = 0; kk < KT; kk++) {
            float au[8], ai[8], wu[4], wi[4];
            #pragma unroll
            for (int i = 0; i < 8; i++) {
                au[i] = sAu[kk][tx + 16 * i];
                ai[i] = sAi[kk][tx + 16 * i];
            }
            #pragma unroll
            for (int j = 0; j < 4; j++) {
                wu[j] = sWu[ty * 4 + j][kk];
                wi[j] = sWi[ty * 4 + j][kk];
            }
            #pragma unroll
            for (int i = 0; i < 8; i++)
                #pragma unroll
                for (int j = 0; j < 4; j++) {
                    accU[i][j] += au[i] * wu[j];
                    accI[i][j] += ai[i] * wi[j];
                }
        }
        __syncthreads();
    }

    #pragma unroll
    for (int j = 0; j < 4; j++) {
        int n = n0 + ty * 4 + j;
        float bun = bu[n], bin = bi[n];
        #pragma unroll
        for (int i = 0; i < 8; i++) {
            int m = m0 + tx + 16 * i;
            float uf = tanhf(accU[i][j] + bun);
            float itf = sigmoidf(accI[i][j] + bin);
            g_XT[(size_t)n * BATCH + m] = (uf - itf) * g_disc[m];
        }
    }
}

// ---------------- kernel 3: GEMM layer 2 (512 -> 256) + sigmoid -------------
__global__ __launch_bounds__(256) void gemm_layer2(
    const float* __restrict__ W1, const float* __restrict__ b1)
{
    const int KT = 16;
    __shared__ float sA[KT][128];
    __shared__ float sW[64][20];

    const int tid = threadIdx.x;
    const int tx = tid & 15;
    const int ty = tid >> 4;
    const int m0 = blockIdx.x * 128;
    const int n0 = blockIdx.y * 64;

    float acc[8][4];
    #pragma unroll
    for (int i = 0; i < 8; i++)
        #pragma unroll
        for (int j = 0; j < 4; j++) acc[i][j] = 0.f;

    for (int k0 = 0; k0 < DIM_HIDDEN; k0 += KT) {
        #pragma unroll
        for (int r = 0; r < 2; r++) {
            int idx = tid + 256 * r;
            int kk = idx >> 5, mv = idx & 31;
            *(float4*)&sA[kk][mv * 4] =
                *(const float4*)&g_XT[(size_t)(k0 + kk) * BATCH + m0 + mv * 4];
        }
        {
            int n = tid >> 2, kv = tid & 3;
            *(float4*)&sW[n][kv * 4] =
                *(const float4*)&W1[(size_t)(n0 + n) * DIM_HIDDEN + k0 + kv * 4];
        }
        __syncthreads();
        #pragma unroll
        for (int kk = 0; kk < KT; kk++) {
            float a[8], w[4];
            #pragma unroll
            for (int i = 0; i < 8; i++) a[i] = sA[kk][tx + 16 * i];
            #pragma unroll
            for (int j = 0; j < 4; j++) w[j] = sW[ty * 4 + j][kk];
            #pragma unroll
            for (int i = 0; i < 8; i++)
                #pragma unroll
                for (int j = 0; j < 4; j++) acc[i][j] += a[i] * w[j];
        }
        __syncthreads();
    }

    #pragma unroll
    for (int j = 0; j < 4; j++) {
        int n = n0 + ty * 4 + j;
        float bn = b1[n];
        #pragma unroll
        for (int i = 0; i < 8; i++) {
            int m = m0 + tx + 16 * i;
            g_HT[(size_t)n * BATCH + m] = sigmoidf(acc[i][j] + bn);
        }
    }
}

// ---------------- kernel 4: final matvec (256 -> 1) + sigmoid ---------------
__global__ __launch_bounds__(256) void final_kernel(
    const float* __restrict__ W2, const float* __restrict__ b2,
    float* __restrict__ out)
{
    __shared__ float w[H2];
    const int tid = threadIdx.x;
    w[tid] = W2[tid];
    __syncthreads();
    const int m = blockIdx.x * 256 + tid;
    float s = b2[0];
    #pragma unroll 8
    for (int k = 0; k < H2; k++)
        s += g_HT[(size_t)k * BATCH + m] * w[k];
    out[m] = sigmoidf(s);
}

// ---------------- launch -----------------------------------------------------
extern "C" void kernel_launch(void* const* d_in, const int* in_sizes, int n_in,
                              void* d_out, int out_size)
{
    Graph g;
    build_graph(g);   // pure host compute, deterministic, runs every call

    const int*   user_id     = (const int*)d_in[0];
    const int*   question_id = (const int*)d_in[1];
    const float* priori      = (const float*)d_in[2];
    const float* condi_p     = (const float*)d_in[3];
    const float* condi_n     = (const float*)d_in[4];
    const float* item_diff   = (const float*)d_in[5];
    const float* item_disc   = (const float*)d_in[6];
    const float* q_table     = (const float*)d_in[7];
    const float* Wu          = (const float*)d_in[8];
    const float* bu          = (const float*)d_in[9];
    const float* Wi          = (const float*)d_in[10];
    const float* bi          = (const float*)d_in[11];
    const float* W1          = (const float*)d_in[12];
    const float* b1          = (const float*)d_in[13];
    const float* W2          = (const float*)d_in[14];
    const float* b2          = (const float*)d_in[15];
    float* out = (float*)d_out;

    const int E = in_sizes[3] / NUM_USER;   // edge count from input layout

    posterior_kernel<<<BATCH / 64, 64>>>(g, user_id, question_id, priori,
                                         condi_p, condi_n, item_diff,
                                         item_disc, q_table, E);

    dim3 grid1(BATCH / 128, DIM_HIDDEN / 64);
    gemm_layer1<<<grid1, 256>>>(Wu, Wi, bu, bi);

    dim3 grid2(BATCH / 128, H2 / 64);
    gemm_layer2<<<grid2, 256>>>(W1, b1);

    final_kernel<<<BATCH / 256, 256>>>(W2, b2, out);
}

// round 2
// speedup vs baseline: 1.7992x; 1.7992x over previous
#include <cuda_runtime.h>
#include <cuda_bf16.h>
#include <cstdint>

#define NUM_USER 200000
#define NUM_QUESTION 20000
#define NUM_CONCEPT 128
#define DIM_HIDDEN 512
#define H2 256
#define BATCH 16384
#define EMAX 400

// ---------------- scratch (device globals; no allocations allowed) ----------
__device__ float g_bp[BATCH * NUM_CONCEPT];      // sigmoid(priori) row-major [b][k]
__device__ float g_cp[BATCH * EMAX];             // pow(sigmoid(condi_p),1/l) [b][e]
__device__ float g_cn[BATCH * EMAX];
__device__ float g_qT[NUM_CONCEPT * BATCH];      // q gathered, feature-major [k][b]
__device__ float g_AuT[NUM_CONCEPT * BATCH];     // post*q, feature-major
__device__ float g_AiT[NUM_CONCEPT * BATCH];     // sigmoid(diff)*q, feature-major
__device__ float g_disc[BATCH];
__device__ float g_XT[DIM_HIDDEN * BATCH];       // layer-1 output, feature-major
__device__ float g_H[BATCH * H2];                // layer-2 output, row-major

// ---------------- graph structure (replicated numpy RandomState(0)) ---------
struct Graph {
    int E;
    unsigned char lp[NUM_CONCEPT];
    short off[NUM_CONCEPT];
    unsigned char pred[NUM_CONCEPT][3];
};
struct EdgeParams {
    int E;
    float invl[EMAX];
};

struct MT19937 {
    uint32_t mt[624];
    int mti;
    void seed(uint32_t s) {
        mt[0] = s;
        for (int i = 1; i < 624; i++)
            mt[i] = 1812433253u * (mt[i - 1] ^ (mt[i - 1] >> 30)) + (uint32_t)i;
        mti = 624;
    }
    uint32_t next() {
        if (mti >= 624) {
            for (int i = 0; i < 624; i++) {
                uint32_t y = (mt[i] & 0x80000000u) | (mt[(i + 1) % 624] & 0x7fffffffu);
                uint32_t v = mt[(i + 397) % 624] ^ (y >> 1);
                if (y & 1u) v ^= 0x9908b0dfu;
                mt[i] = v;
            }
            mti = 0;
        }
        uint32_t y = mt[mti++];
        y ^= y >> 11;
        y ^= (y << 7) & 0x9d2c5680u;
        y ^= (y << 15) & 0xefc60000u;
        y ^= y >> 18;
        return y;
    }
    uint32_t interval(uint32_t mx) {
        if (mx == 0) return 0;
        uint32_t mask = mx;
        mask |= mask >> 1; mask |= mask >> 2; mask |= mask >> 4;
        mask |= mask >> 8; mask |= mask >> 16;
        uint32_t v;
        do { v = next() & mask; } while (v > mx);
        return v;
    }
};

static void build_graph(Graph& g, EdgeParams& ep) {
    MT19937 r;
    r.seed(0u);
    int E = 0;
    for (int k = 0; k < NUM_CONCEPT; k++) {
        int l = 0;
        if (k > 0) {
            int hi = (k < 3) ? k : 3;
            l = (int)r.interval((uint32_t)hi);
        }
        g.lp[k] = (unsigned char)l;
        g.off[k] = (short)E;
        g.pred[k][0] = g.pred[k][1] = g.pred[k][2] = 0;
        if (l > 0) {
            int perm[NUM_CONCEPT];
            for (int i = 0; i < k; i++) perm[i] = i;
            for (int i = k - 1; i >= 1; i--) {
                int j = (int)r.interval((uint32_t)i);
                int t = perm[i]; perm[i] = perm[j]; perm[j] = t;
            }
            int p[3];
            for (int j = 0; j < l; j++) p[j] = perm[j];
            for (int a = 0; a < l; a++)
                for (int b = a + 1; b < l; b++)
                    if (p[b] < p[a]) { int t = p[a]; p[a] = p[b]; p[b] = t; }
            for (int j = 0; j < l; j++) {
                g.pred[k][j] = (unsigned char)p[j];
                ep.invl[E + j] = 1.0f / (float)l;
            }
        }
        E += l;
    }
    g.E = E;
    ep.E = E;
}

// ---------------- device helpers --------------------------------------------
__device__ __forceinline__ float sigmoidf(float x) {
    return 1.0f / (1.0f + __expf(-x));
}
__device__ __forceinline__ float to_tf32(float x) {
    unsigned u;
    asm("cvt.rna.tf32.f32 %0, %1;" : "=r"(u) : "f"(x));
    return __uint_as_float(u);
}
__device__ __forceinline__ void mma_tf32(float* c, const unsigned* a, const unsigned* b) {
    asm volatile(
        "mma.sync.aligned.m16n8k8.row.col.f32.tf32.tf32.f32 "
        "{%0,%1,%2,%3}, {%4,%5,%6,%7}, {%8,%9}, {%0,%1,%2,%3};\n"
        : "+f"(c[0]), "+f"(c[1]), "+f"(c[2]), "+f"(c[3])
        : "r"(a[0]), "r"(a[1]), "r"(a[2]), "r"(a[3]), "r"(b[0]), "r"(b[1]));
}

// ---------------- kernel A: elementwise precompute + gathers/transposes -----
// Block handles 32 batch elements; 256 threads.
__global__ __launch_bounds__(256) void precompute_kernel(
    EdgeParams ep,
    const int* __restrict__ user_id, const int* __restrict__ question_id,
    const float* __restrict__ priori, const float* __restrict__ condi_p,
    const float* __restrict__ condi_n, const float* __restrict__ item_diff,
    const float* __restrict__ item_disc, const float* __restrict__ q_table)
{
    __shared__ int su[32], sq[32];
    __shared__ float s_ai[128 * 33];
    __shared__ float s_q[128 * 33];

    const int tid = threadIdx.x;
    const int b0 = blockIdx.x * 32;
    const int E = ep.E;

    if (tid < 32) {
        su[tid] = user_id[b0 + tid];
        sq[tid] = question_id[b0 + tid];
        g_disc[b0 + tid] = sigmoidf(item_disc[sq[tid]]);
    }
    __syncthreads();

    // bp: 2 rows per iteration, 128 cols each
    {
        const int r = tid >> 7;          // 0/1
        const int c = tid & 127;
        #pragma unroll 4
        for (int i = 0; i < 16; i++) {
            const int bl = i * 2 + r;
            const int u = su[bl];
            float v = sigmoidf(priori[(size_t)u * NUM_CONCEPT + c]);
            g_bp[(size_t)(b0 + bl) * NUM_CONCEPT + c] = v;
        }
    }

    // cp / cn with per-edge exponent
    for (int bl = 0; bl < 32; bl++) {
        const int u = su[bl];
        for (int e = tid; e < E; e += 256) {
            float iv = ep.invl[e];
            float p = sigmoidf(condi_p[(size_t)u * E + e]);
            float n = sigmoidf(condi_n[(size_t)u * E + e]);
            if (iv == 0.5f) { p = sqrtf(p); n = sqrtf(n); }
            else if (iv != 1.0f) {
                p = __powf(p, iv);
                n = __powf(n, iv);
            }
            g_cp[(size_t)(b0 + bl) * EMAX + e] = p;
            g_cn[(size_t)(b0 + bl) * EMAX + e] = n;
        }
    }

    // AiT + qT via smem transpose
    {
        const int r = tid >> 7;
        const int c = tid & 127;
        #pragma unroll 4
        for (int i = 0; i < 16; i++) {
            const int bl = i * 2 + r;
            const int q = sq[bl];
            float qv = q_table[(size_t)q * NUM_CONCEPT + c];
            float dv = sigmoidf(item_diff[(size_t)q * NUM_CONCEPT + c]);
            s_ai[c * 33 + bl] = dv * qv;
            s_q[c * 33 + bl] = qv;
        }
    }
    __syncthreads();
    {
        const int k = tid >> 5;          // 0..7 per pass
        const int bl = tid & 31;
        #pragma unroll 4
        for (int i = 0; i < 16; i++) {
            const int kk = i * 8 + k;
            g_AiT[(size_t)kk * BATCH + b0 + bl] = s_ai[kk * 33 + bl];
            g_qT[(size_t)kk * BATCH + b0 + bl] = s_q[kk * 33 + bl];
        }
    }
}

// ---------------- kernel B: sequential DAG (pure FMA) -----------------------
__global__ __launch_bounds__(64) void dag_kernel(Graph g)
{
    __shared__ float post[NUM_CONCEPT * 64];
    const int tid = threadIdx.x;
    const int b = blockIdx.x * 64 + tid;
    const float* __restrict__ bpr = g_bp + (size_t)b * NUM_CONCEPT;
    const float* __restrict__ cpr = g_cp + (size_t)b * EMAX;
    const float* __restrict__ cnr = g_cn + (size_t)b * EMAX;

    for (int k = 0; k < NUM_CONCEPT; k++) {
        const int l = g.lp[k];
        float pk;
        if (l == 0) {
            pk = bpr[k];
        } else {
            const int o = g.off[k];
            float prod = 1.0f;
            #pragma unroll 3
            for (int j = 0; j < 3; j++) {
                if (j >= l) break;
                float pr = post[(int)g.pred[k][j] * 64 + tid];
                float cp = cpr[o + j];
                float cn = cnr[o + j];
                prod *= cn + pr * (cp - cn);
            }
            pk = prod;
        }
        post[k * 64 + tid] = pk;
        g_AuT[(size_t)k * BATCH + b] = pk * g_qT[(size_t)k * BATCH + b];
    }
}

// ---------------- kernel C: dual tf32 GEMM layer 1 + fused epilogue ---------
// C[16384,512] = A[16384,128] @ W[512,128]^T for u and i; BM=128 BN=64 Kc=64.
__global__ __launch_bounds__(256, 1) void gemm_layer1(
    const float* __restrict__ Wu, const float* __restrict__ Wi,
    const float* __restrict__ bu, const float* __restrict__ bi)
{
    extern __shared__ float smem[];
    float* sAu = smem;                 // [64][132]
    float* sAi = smem + 8448;          // [64][132]
    float* sWu = smem + 16896;         // [64][68]
    float* sWi = smem + 16896 + 4352;  // [64][68]

    const int tid = threadIdx.x;
    const int lane = tid & 31;
    const int wid = tid >> 5;
    const int wm = wid & 3;            // 4 warps along m
    const int wn = wid >> 2;           // 2 warps along n
    const int r = lane >> 2;
    const int cq = lane & 3;
    const int m0 = blockIdx.x * 128;
    const int n0 = blockIdx.y * 64;

    float accU[2][4][4], accI[2][4][4];
    #pragma unroll
    for (int mi = 0; mi < 2; mi++)
        #pragma unroll
        for (int ni = 0; ni < 4; ni++)
            #pragma unroll
            for (int t = 0; t < 4; t++) { accU[mi][ni][t] = 0.f; accI[mi][ni][t] = 0.f; }

    for (int kc = 0; kc < 2; kc++) {
        // stage A tiles (feature-major source, coalesced)
        #pragma unroll
        for (int f0 = 0; f0 < 2048; f0 += 256) {
            int f = f0 + tid;
            int k = f >> 5, mq = f & 31;
            float4 v = *(const float4*)&g_AuT[(size_t)(kc * 64 + k) * BATCH + m0 + mq * 4];
            v.x = to_tf32(v.x); v.y = to_tf32(v.y); v.z = to_tf32(v.z); v.w = to_tf32(v.w);
            *(float4*)&sAu[k * 132 + mq * 4] = v;
            float4 w = *(const float4*)&g_AiT[(size_t)(kc * 64 + k) * BATCH + m0 + mq * 4];
            w.x = to_tf32(w.x); w.y = to_tf32(w.y); w.z = to_tf32(w.z); w.w = to_tf32(w.w);
            *(float4*)&sAi[k * 132 + mq * 4] = w;
        }
        // stage W tiles
        #pragma unroll
        for (int f0 = 0; f0 < 1024; f0 += 256) {
            int f = f0 + tid;
            int n = f >> 4, kq = f & 15;
            float4 v = *(const float4*)&Wu[(size_t)(n0 + n) * NUM_CONCEPT + kc * 64 + kq * 4];
            v.x = to_tf32(v.x); v.y = to_tf32(v.y); v.z = to_tf32(v.z); v.w = to_tf32(v.w);
            *(float4*)&sWu[n * 68 + kq * 4] = v;
            float4 w = *(const float4*)&Wi[(size_t)(n0 + n) * NUM_CONCEPT + kc * 64 + kq * 4];
            w.x = to_tf32(w.x); w.y = to_tf32(w.y); w.z = to_tf32(w.z); w.w = to_tf32(w.w);
            *(float4*)&sWi[n * 68 + kq * 4] = w;
        }
        __syncthreads();

        #pragma unroll
        for (int kk = 0; kk < 64; kk += 8) {
            unsigned aU[2][4], aI[2][4], bU[4][2], bI[4][2];
            #pragma unroll
            for (int mi = 0; mi < 2; mi++) {
                int m = wm * 32 + mi * 16 + r;
                const float* p0 = &sAu[(kk + cq) * 132 + m];
                const float* p1 = &sAu[(kk + 4 + cq) * 132 + m];
                aU[mi][0] = __float_as_uint(p0[0]);
                aU[mi][1] = __float_as_uint(p0[8]);
                aU[mi][2] = __float_as_uint(p1[0]);
                aU[mi][3] = __float_as_uint(p1[8]);
                const float* q0 = &sAi[(kk + cq) * 132 + m];
                const float* q1 = &sAi[(kk + 4 + cq) * 132 + m];
                aI[mi][0] = __float_as_uint(q0[0]);
                aI[mi][1] = __float_as_uint(q0[8]);
                aI[mi][2] = __float_as_uint(q1[0]);
                aI[mi][3] = __float_as_uint(q1[8]);
            }
            #pragma unroll
            for (int ni = 0; ni < 4; ni++) {
                int n = wn * 32 + ni * 8 + r;
                bU[ni][0] = __float_as_uint(sWu[n * 68 + kk + cq]);
                bU[ni][1] = __float_as_uint(sWu[n * 68 + kk + 4 + cq]);
                bI[ni][0] = __float_as_uint(sWi[n * 68 + kk + cq]);
                bI[ni][1] = __float_as_uint(sWi[n * 68 + kk + 4 + cq]);
            }
            #pragma unroll
            for (int mi = 0; mi < 2; mi++)
                #pragma unroll
                for (int ni = 0; ni < 4; ni++) {
                    mma_tf32(accU[mi][ni], aU[mi], bU[ni]);
                    mma_tf32(accI[mi][ni], aI[mi], bI[ni]);
                }
        }
        __syncthreads();
    }

    // epilogue: x = (tanh(u+bu) - sigmoid(i+bi)) * disc, transpose via smem
    float* sX = smem;  // [64][132] n x m
    #pragma unroll
    for (int mi = 0; mi < 2; mi++) {
        int ml0 = wm * 32 + mi * 16 + r;
        int ml1 = ml0 + 8;
        float d0 = g_disc[m0 + ml0];
        float d1 = g_disc[m0 + ml1];
        #pragma unroll
        for (int ni = 0; ni < 4; ni++) {
            int nl0 = wn * 32 + ni * 8 + 2 * cq;
            int nl1 = nl0 + 1;
            float bu0 = bu[n0 + nl0], bu1 = bu[n0 + nl1];
            float bi0 = bi[n0 + nl0], bi1 = bi[n0 + nl1];
            float* aU = accU[mi][ni];
            float* aI = accI[mi][ni];
            sX[nl0 * 132 + ml0] = (tanhf(aU[0] + bu0) - sigmoidf(aI[0] + bi0)) * d0;
            sX[nl1 * 132 + ml0] = (tanhf(aU[1] + bu1) - sigmoidf(aI[1] + bi1)) * d0;
            sX[nl0 * 132 + ml1] = (tanhf(aU[2] + bu0) - sigmoidf(aI[2] + bi0)) * d1;
            sX[nl1 * 132 + ml1] = (tanhf(aU[3] + bu1) - sigmoidf(aI[3] + bi1)) * d1;
        }
    }
    __syncthreads();
    #pragma unroll
    for (int f0 = 0; f0 < 2048; f0 += 256) {
        int f = f0 + tid;
        int nl = f >> 5, mq = f & 31;
        *(float4*)&g_XT[(size_t)(n0 + nl) * BATCH + m0 + mq * 4] =
            *(const float4*)&sX[nl * 132 + mq * 4];
    }
}

// ---------------- kernel D: tf32 GEMM layer 2 (K=512 -> N=256) + sigmoid ----
__global__ __launch_bounds__(256, 1) void gemm_layer2(
    const float* __restrict__ W1, const float* __restrict__ b1)
{
    extern __shared__ float smem[];
    float* sA = smem;            // [64][132]
    float* sW = smem + 8448;     // [64][68]

    const int tid = threadIdx.x;
    const int lane = tid & 31;
    const int wid = tid >> 5;
    const int wm = wid & 3;
    const int wn = wid >> 2;
    const int r = lane >> 2;
    const int cq = lane & 3;
    const int m0 = blockIdx.x * 128;
    const int n0 = blockIdx.y * 64;

    float acc[2][4][4];
    #pragma unroll
    for (int mi = 0; mi < 2; mi++)
        #pragma unroll
        for (int ni = 0; ni < 4; ni++)
            #pragma unroll
            for (int t = 0; t < 4; t++) acc[mi][ni][t] = 0.f;

    for (int kc = 0; kc < 8; kc++) {
        #pragma unroll
        for (int f0 = 0; f0 < 2048; f0 += 256) {
            int f = f0 + tid;
            int k = f >> 5, mq = f & 31;
            float4 v = *(const float4*)&g_XT[(size_t)(kc * 64 + k) * BATCH + m0 + mq * 4];
            v.x = to_tf32(v.x); v.y = to_tf32(v.y); v.z = to_tf32(v.z); v.w = to_tf32(v.w);
            *(float4*)&sA[k * 132 + mq * 4] = v;
        }
        #pragma unroll
        for (int f0 = 0; f0 < 1024; f0 += 256) {
            int f = f0 + tid;
            int n = f >> 4, kq = f & 15;
            float4 v = *(const float4*)&W1[(size_t)(n0 + n) * DIM_HIDDEN + kc * 64 + kq * 4];
            v.x = to_tf32(v.x); v.y = to_tf32(v.y); v.z = to_tf32(v.z); v.w = to_tf32(v.w);
            *(float4*)&sW[n * 68 + kq * 4] = v;
        }
        __syncthreads();

        #pragma unroll
        for (int kk = 0; kk < 64; kk += 8) {
            unsigned a[2][4], b[4][2];
            #pragma unroll
            for (int mi = 0; mi < 2; mi++) {
                int m = wm * 32 + mi * 16 + r;
                const float* p0 = &sA[(kk + cq) * 132 + m];
                const float* p1 = &sA[(kk + 4 + cq) * 132 + m];
                a[mi][0] = __float_as_uint(p0[0]);
                a[mi][1] = __float_as_uint(p0[8]);
                a[mi][2] = __float_as_uint(p1[0]);
                a[mi][3] = __float_as_uint(p1[8]);
            }
            #pragma unroll
            for (int ni = 0; ni < 4; ni++) {
                int n = wn * 32 + ni * 8 + r;
                b[ni][0] = __float_as_uint(sW[n * 68 + kk + cq]);
                b[ni][1] = __float_as_uint(sW[n * 68 + kk + 4 + cq]);
            }
            #pragma unroll
            for (int mi = 0; mi < 2; mi++)
                #pragma unroll
                for (int ni = 0; ni < 4; ni++)
                    mma_tf32(acc[mi][ni], a[mi], b[ni]);
        }
        __syncthreads();
    }

    // epilogue: sigmoid, row-major float2 stores
    #pragma unroll
    for (int mi = 0; mi < 2; mi++) {
        int mg0 = m0 + wm * 32 + mi * 16 + r;
        int mg1 = mg0 + 8;
        #pragma unroll
        for (int ni = 0; ni < 4; ni++) {
            int ng = n0 + wn * 32 + ni * 8 + 2 * cq;
            float b0 = b1[ng], b1v = b1[ng + 1];
            float* a = acc[mi][ni];
            float2 v0 = make_float2(sigmoidf(a[0] + b0), sigmoidf(a[1] + b1v));
            float2 v1 = make_float2(sigmoidf(a[2] + b0), sigmoidf(a[3] + b1v));
            *(float2*)&g_H[(size_t)mg0 * H2 + ng] = v0;
            *(float2*)&g_H[(size_t)mg1 * H2 + ng] = v1;
        }
    }
}

// ---------------- kernel E: final matvec (256 -> 1) + sigmoid ---------------
__global__ __launch_bounds__(256) void final_kernel(
    const float* __restrict__ W2, const float* __restrict__ b2,
    float* __restrict__ out)
{
    __shared__ float w[H2];
    const int tid = threadIdx.x;
    const int lane = tid & 31;
    const int wid = tid >> 5;
    w[tid] = W2[tid];
    __syncthreads();
    const int m = blockIdx.x * 8 + wid;
    const float4* hp = (const float4*)(g_H + (size_t)m * H2);
    float s = 0.f;
    #pragma unroll
    for (int i = 0; i < 2; i++) {
        int idx = lane * 2 + i;                 // 0..63 float4s
        float4 v = hp[idx];
        int k = idx * 4;
        s += v.x * w[k] + v.y * w[k + 1] + v.z * w[k + 2] + v.w * w[k + 3];
    }
    #pragma unroll
    for (int off = 16; off > 0; off >>= 1)
        s += __shfl_xor_sync(0xffffffffu, s, off);
    if (lane == 0) out[m] = sigmoidf(s + b2[0]);
}

// ---------------- launch -----------------------------------------------------
extern "C" void kernel_launch(void* const* d_in, const int* in_sizes, int n_in,
                              void* d_out, int out_size)
{
    Graph g;
    EdgeParams ep;
    build_graph(g, ep);

    const int*   user_id     = (const int*)d_in[0];
    const int*   question_id = (const int*)d_in[1];
    const float* priori      = (const float*)d_in[2];
    const float* condi_p     = (const float*)d_in[3];
    const float* condi_n     = (const float*)d_in[4];
    const float* item_diff   = (const float*)d_in[5];
    const float* item_disc   = (const float*)d_in[6];
    const float* q_table     = (const float*)d_in[7];
    const float* Wu          = (const float*)d_in[8];
    const float* bu          = (const float*)d_in[9];
    const float* Wi          = (const float*)d_in[10];
    const float* bi          = (const float*)d_in[11];
    const float* W1          = (const float*)d_in[12];
    const float* b1          = (const float*)d_in[13];
    const float* W2          = (const float*)d_in[14];
    const float* b2          = (const float*)d_in[15];
    float* out = (float*)d_out;

    cudaFuncSetAttribute(gemm_layer1, cudaFuncAttributeMaxDynamicSharedMemorySize, 102400);
    cudaFuncSetAttribute(gemm_layer2, cudaFuncAttributeMaxDynamicSharedMemorySize, 51200);

    precompute_kernel<<<BATCH / 32, 256>>>(ep, user_id, question_id, priori,
                                           condi_p, condi_n, item_diff,
                                           item_disc, q_table);

    dag_kernel<<<BATCH / 64, 64>>>(g);

    dim3 grid1(BATCH / 128, DIM_HIDDEN / 64);
    gemm_layer1<<<grid1, 256, 102400>>>(Wu, Wi, bu, bi);

    dim3 grid2(BATCH / 128, H2 / 64);
    gemm_layer2<<<grid2, 256, 51200>>>(W1, b1);

    final_kernel<<<BATCH / 8, 256>>>(W2, b2, out);
}